// round 2
// baseline (speedup 1.0000x reference)
#include <cuda_runtime.h>

#define N_NODES 10000
#define IN_CH   128
#define OUT_CH  64
#define NSTEP   16
#define E_EDGES 320000
#define K_SEL   (E_EDGES/2)
#define NB      16
#define TIE_CAP 65536
#define KPT     12          // max edges owned per thread in select kernel

// ---------------- device scratch ----------------
__device__ float         g_beta[N_NODES*NSTEP];
__device__ float         g_mean_beta[N_NODES];
__device__ float         g_val[N_NODES*OUT_CH];
__device__ unsigned char g_flags[E_EDGES];
__device__ float         g_denom[N_NODES*NSTEP];
__device__ unsigned int  g_hist[256];
__device__ unsigned int  g_prefix;
__device__ int           g_kneed;
__device__ unsigned int  g_thresh;
__device__ int           g_R;
__device__ int           g_tie_cnt;
__device__ int           g_tie_list[TIE_CAP];
__device__ unsigned int  g_bar_cnt;   // barrier state persists across replays:
__device__ unsigned int  g_bar_gen;   // cnt returns to 0, gen monotonic

// order-preserving float->uint (ascending)
__device__ __forceinline__ unsigned int fxform(float f) {
    unsigned int u = __float_as_uint(f);
    return (u & 0x80000000u) ? ~u : (u | 0x80000000u);
}

// software grid-wide barrier (all blocks must be co-resident)
__device__ __forceinline__ void gbar() {
    __syncthreads();
    if (threadIdx.x == 0) {
        volatile unsigned int* gen_p = &g_bar_gen;
        unsigned int gen = *gen_p;
        __threadfence();
        if (atomicAdd(&g_bar_cnt, 1u) == gridDim.x - 1) {
            g_bar_cnt = 0;
            __threadfence();
            *gen_p = gen + 1u;
        } else {
            while (*gen_p == gen) { }
        }
        __threadfence();
    }
    __syncthreads();
}

// ---------------- node GEMMs + beta reduction (+ folded init) ----------------
__global__ __launch_bounds__(256) void node_kernel(
    const float* __restrict__ x,
    const float* __restrict__ p_t,
    const float* __restrict__ Wv, const float* __restrict__ bv,
    const float* __restrict__ Wi, const float* __restrict__ bi,
    const float* __restrict__ mw,
    float* __restrict__ out)
{
    __shared__ float xsT[IN_CH][NB];
    __shared__ float hwS[NB][16][33];
    __shared__ float betaS[NB][17];

    int tid   = threadIdx.x;
    int node0 = blockIdx.x * NB;

    // folded init (consumed only by the next kernel)
    {
        int i = blockIdx.x * 256 + tid;
        int stride = gridDim.x * 256;
        for (int idx = i; idx < N_NODES*OUT_CH; idx += stride) out[idx] = 0.0f;
        for (int idx = i; idx < N_NODES*NSTEP; idx += stride) g_denom[idx] = 0.0f;
        if (i < 256) g_hist[i] = 0u;
        if (i == 0) { g_prefix = 0u; g_kneed = K_SEL; g_tie_cnt = 0; }
    }

    for (int idx = tid; idx < NB*IN_CH; idx += 256) {
        int n = idx >> 7, k = idx & 127;
        xsT[k][n] = x[(node0 + n)*IN_CH + k];
    }
    __syncthreads();

    float acc0[NB], acc1[NB], acc2[NB];
    #pragma unroll
    for (int n = 0; n < NB; n++) { acc0[n] = 0.f; acc1[n] = 0.f; acc2[n] = 0.f; }

    const bool has_v = (tid < 64);
    for (int k = 0; k < IN_CH; k++) {
        float w0 = Wi[k*512 + tid];
        float w1 = Wi[k*512 + tid + 256];
        float w2 = has_v ? Wv[k*64 + tid] : 0.0f;
        #pragma unroll
        for (int n = 0; n < NB; n++) {
            float xv = xsT[k][n];
            acc0[n] = fmaf(xv, w0, acc0[n]);
            acc1[n] = fmaf(xv, w1, acc1[n]);
            acc2[n] = fmaf(xv, w2, acc2[n]);
        }
    }

    {
        int s0 = tid >> 5, k0 = tid & 31;
        float b0 = bi[tid], b1 = bi[tid + 256];
        #pragma unroll
        for (int n = 0; n < NB; n++) {
            hwS[n][s0][k0]     = acc0[n] + b0;
            hwS[n][s0 + 8][k0] = acc1[n] + b1;
        }
    }
    if (has_v) {
        float bvv = bv[tid];
        #pragma unroll
        for (int n = 0; n < NB; n++) {
            float v = acc2[n] + bvv;
            g_val[(node0 + n)*64 + tid] = v > 0.f ? v : 0.f;
        }
    }
    __syncthreads();

    {
        int n = tid >> 4, s = tid & 15;
        const float* mwrow = mw + (node0 + n)*16;
        const float* ptrow = p_t + s*16;
        float sum = 0.f;
        #pragma unroll
        for (int k = 0; k < 16; k++) sum = fmaf(hwS[n][s][k],      mwrow[k], sum);
        #pragma unroll
        for (int k = 0; k < 16; k++) sum = fmaf(hwS[n][s][16 + k], ptrow[k], sum);
        float b = sum * (1.0f/32.0f);
        betaS[n][s] = b;
        g_beta[(node0 + n)*NSTEP + s] = b;
    }
    __syncthreads();
    if (tid < NB) {
        float s = 0.f;
        #pragma unroll
        for (int k = 0; k < NSTEP; k++) s += betaS[tid][k];
        g_mean_beta[node0 + tid] = s * (1.0f/NSTEP);
    }
}

// ---------------- persistent: keys + radix select + flags + softmax-accum + divide ----------------
__global__ __launch_bounds__(256, 4) void select_kernel(
    const int* __restrict__ ei, const float* __restrict__ ew,
    float* __restrict__ out)
{
    const int T    = gridDim.x * blockDim.x;
    const int gtid = blockIdx.x * blockDim.x + threadIdx.x;
    __shared__ unsigned int sh[256];

    // ---- phase 0: keys into registers ----
    unsigned int keys[KPT];
    int nk = 0;
    #pragma unroll
    for (int j = 0; j < KPT; j++) {
        int e = gtid + j*T;
        if (e < E_EDGES) {
            int dst = ei[E_EDGES + e];
            float s = ew[e] * g_mean_beta[dst];
            s += 0.0f;                    // -0 -> +0 (reference treats them equal)
            keys[j] = fxform(s);
            nk = j + 1;
        }
    }

    // ---- 4 radix passes over register-resident keys ----
    for (int pass = 0; pass < 4; pass++) {
        int shift = 24 - 8*pass;
        unsigned int pref = *(volatile unsigned int*)&g_prefix;
        sh[threadIdx.x] = 0u;
        __syncthreads();
        for (int j = 0; j < nk; j++) {
            unsigned int k = keys[j];
            bool m = (pass == 0) || ((k >> (shift + 8)) == pref);
            if (m) atomicAdd(&sh[(k >> shift) & 255u], 1u);
        }
        __syncthreads();
        if (sh[threadIdx.x]) atomicAdd(&g_hist[threadIdx.x], sh[threadIdx.x]);
        gbar();
        if (blockIdx.x == 0) {
            sh[threadIdx.x] = *(volatile unsigned int*)&g_hist[threadIdx.x];
            __syncthreads();
            if (threadIdx.x == 0) {
                int kneed = g_kneed;
                unsigned int cum = 0u;
                unsigned int p2  = g_prefix;
                for (int b = 255; b >= 0; b--) {
                    unsigned int c = sh[b];
                    if (cum + c >= (unsigned int)kneed) {
                        g_prefix = (p2 << 8) | (unsigned int)b;
                        g_kneed  = kneed - (int)cum;
                        break;
                    }
                    cum += c;
                }
                if (pass == 3) { g_thresh = g_prefix; g_R = g_kneed; }
            }
            __syncthreads();
            *(volatile unsigned int*)&g_hist[threadIdx.x] = 0u;  // ready for next pass / next replay
        }
        gbar();
    }

    // ---- flags + tie collection ----
    {
        unsigned int thr = *(volatile unsigned int*)&g_thresh;
        for (int j = 0; j < nk; j++) {
            int e = gtid + j*T;
            unsigned int k = keys[j];
            unsigned char f = 0;
            if (k > thr) f = 1;
            else if (k == thr) {
                int p = atomicAdd(&g_tie_cnt, 1);
                if (p < TIE_CAP) g_tie_list[p] = e;
            }
            g_flags[e] = f;
        }
    }
    gbar();
    if (blockIdx.x == 0) {
        int Tt = *(volatile int*)&g_tie_cnt; if (Tt > TIE_CAP) Tt = TIE_CAP;
        int R  = *(volatile int*)&g_R;
        for (int i = threadIdx.x; i < Tt; i += blockDim.x) {
            int idx = ((volatile int*)g_tie_list)[i];
            int r = 0;
            for (int j = 0; j < Tt; j++) r += (((volatile int*)g_tie_list)[j] < idx);
            if (r < R) ((volatile unsigned char*)g_flags)[idx] = 1;  // stable: smallest idx wins
        }
    }
    gbar();

    // ---- softmax numerator+denominator (no max-subtraction: |g| bounded, exp safe) ----
    for (int t = gtid; t < E_EDGES*16; t += T) {
        int e = t >> 4;
        if (((volatile unsigned char*)g_flags)[e]) {
            int l = t & 15;
            int src = ei[e], dst = ei[E_EDGES + e];
            float g  = g_beta[dst*NSTEP + l] * ew[e];
            float ex = __expf(g);
            atomicAdd(&g_denom[src*NSTEP + l], ex);
            const float4 v = *reinterpret_cast<const float4*>(&g_val[dst*64 + l*4]);
            float* o = out + src*64 + l*4;
            atomicAdd(o + 0, v.x * ex);
            atomicAdd(o + 1, v.y * ex);
            atomicAdd(o + 2, v.z * ex);
            atomicAdd(o + 3, v.w * ex);
        }
    }
    gbar();

    // ---- final divide ----
    for (int i = gtid; i < N_NODES*OUT_CH; i += T) {
        int n = i >> 6;
        int s = (i >> 2) & 15;
        float d = *(volatile float*)&g_denom[n*NSTEP + s];
        out[i] = out[i] / (d + 1e-16f);
    }
}

// ---------------- launch ----------------
extern "C" void kernel_launch(void* const* d_in, const int* in_sizes, int n_in,
                              void* d_out, int out_size) {
    const float* x   = (const float*)d_in[0];
    const float* p_t = (const float*)d_in[1];
    const int*   ei  = (const int*)  d_in[2];
    const float* ew  = (const float*)d_in[3];
    const float* Wv  = (const float*)d_in[4];
    const float* bv  = (const float*)d_in[5];
    const float* Wi  = (const float*)d_in[6];
    const float* bi  = (const float*)d_in[7];
    const float* mw  = (const float*)d_in[8];
    float* out = (float*)d_out;

    int dev = 0, sms = 148;
    cudaGetDevice(&dev);
    cudaDeviceGetAttribute(&sms, cudaDevAttrMultiProcessorCount, dev);
    int grid_p = sms * 4;                     // co-resident by __launch_bounds__(256,4)
    // safety: KPT must cover all edges (holds for any sms >= 27)
    if (grid_p * 256 * KPT < E_EDGES) grid_p = (E_EDGES + 256*KPT - 1) / (256*KPT);

    node_kernel<<<N_NODES/NB, 256>>>(x, p_t, Wv, bv, Wi, bi, mw, out);
    select_kernel<<<grid_p, 256>>>(ei, ew, out);
}